// round 2
// baseline (speedup 1.0000x reference)
#include <cuda_runtime.h>
#include <math.h>

#define NB 8
#define NSHOT 5
#define NSB 40          // NB * NSHOT
#define FS 256
#define TILE 64
#define KT 16

// ---------------- scratch (static device globals; no allocation at runtime) ----------------
__device__ float g_P3x[NB*FS*1600];
__device__ float g_P4x[NB*FS*400];
__device__ float g_P5x[NB*FS*100];
__device__ float g_P6x[NB*FS*25];
__device__ float g_s3[NSB*FS*1600];
__device__ float g_s4[NSB*FS*400];
__device__ float g_s5[NSB*FS*100];
__device__ float g_s6[NSB*FS*25];
__device__ float g_s7[NSB*FS*9];
__device__ float g_Qb[NB*FS*1600];
__device__ float g_Kb[NSB*FS*1600];
__device__ float g_scores[(size_t)NSHOT*NB*1600*1600];   // 409.6 MB, level-3 worst case

// ---------------- generic conv-as-GEMM (1x1 or 3x3 implicit im2col) ----------------
// Y[n, o, p] = bias[o] + sum_k W[o,k] * X(n, k-th unrolled input, p)
// Y channel stride = Hout*Wout; batch strides passed explicitly so Y can point
// into the final concatenated output buffer (channel-512 layout).
template<int KSIZE>
__global__ void conv_gemm(const float* __restrict__ X, const float* __restrict__ W,
                          const float* __restrict__ bias, float* __restrict__ Y,
                          int Cin, int Hin, int Win, int Hout, int Wout,
                          int stride, int reluIn, long xBatch, long yBatch)
{
    const int HWout = Hout * Wout;
    const int HWin  = Hin * Win;
    const int Ktot  = Cin * KSIZE * KSIZE;
    const int n  = blockIdx.z;
    const int m0 = blockIdx.y * TILE;       // output-channel tile (M = 256, always full)
    const int p0 = blockIdx.x * TILE;       // pixel tile
    const float* Xn = X + (long)n * xBatch;

    __shared__ float As[KT][TILE + 1];
    __shared__ float Bs[KT][TILE + 1];

    const int tid = threadIdx.x;            // 256 threads
    const int tx = tid & 15, ty = tid >> 4;
    float acc[4][4] = {};

    for (int kk = 0; kk < Ktot; kk += KT) {
        // A tile: W[m0+m][kk+k]  (K always divisible by 16 here)
        #pragma unroll
        for (int i = 0; i < 4; i++) {
            int lin = tid + i * 256;
            int m = lin >> 4, k = lin & 15;
            As[k][m] = W[(long)(m0 + m) * Ktot + kk + k];
        }
        // B tile: gathered input
        #pragma unroll
        for (int i = 0; i < 4; i++) {
            int lin = tid + i * 256;
            int k = lin >> 6, nn = lin & 63;
            int p = p0 + nn;
            float v = 0.f;
            if (p < HWout) {
                int gk = kk + k;
                if (KSIZE == 1) {
                    v = Xn[(long)gk * HWin + p];
                } else {
                    int c = gk / 9, tap = gk - c * 9;
                    int dy = tap / 3, dx = tap - dy * 3;
                    int py = p / Wout, px = p - py * Wout;
                    int iy = py * stride + dy - 1;
                    int ix = px * stride + dx - 1;
                    if (iy >= 0 && iy < Hin && ix >= 0 && ix < Win) {
                        v = Xn[(long)c * HWin + iy * Win + ix];
                        if (reluIn) v = fmaxf(v, 0.f);
                    }
                }
            }
            Bs[k][nn] = v;
        }
        __syncthreads();
        #pragma unroll
        for (int k = 0; k < KT; k++) {
            float a[4], b[4];
            #pragma unroll
            for (int i = 0; i < 4; i++) a[i] = As[k][ty * 4 + i];
            #pragma unroll
            for (int j = 0; j < 4; j++) b[j] = Bs[k][tx * 4 + j];
            #pragma unroll
            for (int i = 0; i < 4; i++)
                #pragma unroll
                for (int j = 0; j < 4; j++) acc[i][j] += a[i] * b[j];
        }
        __syncthreads();
    }

    float* Yn = Y + (long)n * yBatch;
    #pragma unroll
    for (int i = 0; i < 4; i++) {
        int o = m0 + ty * 4 + i;
        float bv = bias[o];
        #pragma unroll
        for (int j = 0; j < 4; j++) {
            int p = p0 + tx * 4 + j;
            if (p < HWout) Yn[(long)o * HWout + p] = acc[i][j] + bv;
        }
    }
}

// ---------------- scores: Scr[(s*8+b), l, m] = scale * sum_o Q[b,o,l]*K[b*5+s,o,m] ----------------
__global__ void scores_gemm(const float* __restrict__ Qg, const float* __restrict__ Kg,
                            float* __restrict__ Scr, int L, float scale)
{
    const int z = blockIdx.z;               // s*8 + b
    const int s = z >> 3, b = z & 7;
    const int l0 = blockIdx.y * TILE;
    const int m0 = blockIdx.x * TILE;
    const float* A  = Qg + (long)b * FS * L;
    const float* Bp = Kg + (long)(b * NSHOT + s) * FS * L;

    __shared__ float As[KT][TILE + 1];
    __shared__ float Bs[KT][TILE + 1];
    const int tid = threadIdx.x;
    const int tx = tid & 15, ty = tid >> 4;
    float acc[4][4] = {};

    for (int kk = 0; kk < FS; kk += KT) {
        #pragma unroll
        for (int i = 0; i < 4; i++) {
            int lin = tid + i * 256;
            int k = lin >> 6, c = lin & 63;
            As[k][c] = (l0 + c < L) ? A [(long)(kk + k) * L + l0 + c] : 0.f;
        }
        #pragma unroll
        for (int i = 0; i < 4; i++) {
            int lin = tid + i * 256;
            int k = lin >> 6, c = lin & 63;
            Bs[k][c] = (m0 + c < L) ? Bp[(long)(kk + k) * L + m0 + c] : 0.f;
        }
        __syncthreads();
        #pragma unroll
        for (int k = 0; k < KT; k++) {
            float a[4], b2[4];
            #pragma unroll
            for (int i = 0; i < 4; i++) a[i]  = As[k][ty * 4 + i];
            #pragma unroll
            for (int j = 0; j < 4; j++) b2[j] = Bs[k][tx * 4 + j];
            #pragma unroll
            for (int i = 0; i < 4; i++)
                #pragma unroll
                for (int j = 0; j < 4; j++) acc[i][j] += a[i] * b2[j];
        }
        __syncthreads();
    }
    #pragma unroll
    for (int i = 0; i < 4; i++) {
        int l = l0 + ty * 4 + i;
        #pragma unroll
        for (int j = 0; j < 4; j++) {
            int m = m0 + tx * 4 + j;
            if (l < L && m < L)
                Scr[((long)z * L + l) * L + m] = acc[i][j] * scale;
        }
    }
}

// ---------------- row softmax over last dim ----------------
__global__ void softmax_rows(float* __restrict__ S, int L)
{
    const long row = blockIdx.x;
    float* p = S + row * (long)L;
    __shared__ float red[256];
    const int tid = threadIdx.x;

    float mx = -1e30f;
    for (int i = tid; i < L; i += 256) mx = fmaxf(mx, p[i]);
    red[tid] = mx; __syncthreads();
    for (int st = 128; st > 0; st >>= 1) {
        if (tid < st) red[tid] = fmaxf(red[tid], red[tid + st]);
        __syncthreads();
    }
    mx = red[0]; __syncthreads();

    float sum = 0.f;
    for (int i = tid; i < L; i += 256) { float e = expf(p[i] - mx); p[i] = e; sum += e; }
    red[tid] = sum; __syncthreads();
    for (int st = 128; st > 0; st >>= 1) {
        if (tid < st) red[tid] += red[tid + st];
        __syncthreads();
    }
    const float inv = 1.f / red[0];
    for (int i = tid; i < L; i += 256) p[i] *= inv;
}

// ---------------- PV: out[b, 256+c, l] = (1/5) * sum_{s,m} Scr[s,b,l,m] * V[b*5+s, c, m] ----------------
__global__ void pv_gemm(const float* __restrict__ Scr, const float* __restrict__ V,
                        float* __restrict__ Ybase, int L, long yBatch)
{
    const int b  = blockIdx.z;
    const int c0 = blockIdx.y * TILE;
    const int l0 = blockIdx.x * TILE;
    const int Ktot = NSHOT * L;

    __shared__ float As[KT][TILE + 1];
    __shared__ float Bs[KT][TILE + 1];
    const int tid = threadIdx.x;
    const int tx = tid & 15, ty = tid >> 4;
    float acc[4][4] = {};

    for (int kk = 0; kk < Ktot; kk += KT) {
        #pragma unroll
        for (int i = 0; i < 4; i++) {
            int lin = tid + i * 256;
            int cl = lin >> 4, k = lin & 15;
            int gk = kk + k;
            float v = 0.f;
            if (gk < Ktot) {
                int s = gk / L, m = gk - s * L;
                v = V[((long)(b * NSHOT + s) * FS + (c0 + cl)) * L + m];
            }
            As[k][cl] = v;
        }
        #pragma unroll
        for (int i = 0; i < 4; i++) {
            int lin = tid + i * 256;
            int ll = lin >> 4, k = lin & 15;
            int gk = kk + k;
            int l = l0 + ll;
            float v = 0.f;
            if (gk < Ktot && l < L) {
                int s = gk / L, m = gk - s * L;
                v = Scr[(((long)(s * 8 + b)) * L + l) * L + m];
            }
            Bs[k][ll] = v;
        }
        __syncthreads();
        #pragma unroll
        for (int k = 0; k < KT; k++) {
            float a[4], b2[4];
            #pragma unroll
            for (int i = 0; i < 4; i++) a[i]  = As[k][ty * 4 + i];
            #pragma unroll
            for (int j = 0; j < 4; j++) b2[j] = Bs[k][tx * 4 + j];
            #pragma unroll
            for (int i = 0; i < 4; i++)
                #pragma unroll
                for (int j = 0; j < 4; j++) acc[i][j] += a[i] * b2[j];
        }
        __syncthreads();
    }

    float* Yn = Ybase + (long)b * yBatch;
    #pragma unroll
    for (int i = 0; i < 4; i++) {
        int c = c0 + ty * 4 + i;
        #pragma unroll
        for (int j = 0; j < 4; j++) {
            int l = l0 + tx * 4 + j;
            if (l < L) Yn[(long)c * L + l] = acc[i][j] * 0.2f;
        }
    }
}

// ---------------- elementwise helpers ----------------
__global__ void up2_add(float* __restrict__ dst, const float* __restrict__ src,
                        int NC, int Hd, int Wd)
{
    int idx = blockIdx.x * blockDim.x + threadIdx.x;
    int tot = NC * Hd * Wd;
    if (idx >= tot) return;
    int x = idx % Wd; int t = idx / Wd;
    int y = t % Hd;   int nc = t / Hd;
    dst[idx] += src[(nc * (Hd >> 1) + (y >> 1)) * (Wd >> 1) + (x >> 1)];
}

__global__ void copy_qx(float* __restrict__ out, const float* __restrict__ src, int HW)
{
    int idx = blockIdx.x * blockDim.x + threadIdx.x;
    int tot = NB * FS * HW;
    if (idx >= tot) return;
    int p = idx % HW; int t = idx / HW;
    int c = t % FS;   int b = t / FS;
    out[(long)b * 512 * HW + (long)c * HW + p] = src[idx];
}

__global__ void add_pe(float* __restrict__ buf, int N, int HW)
{
    long idx = blockIdx.x * (long)blockDim.x + threadIdx.x;
    long tot = (long)N * FS * HW;
    if (idx >= tot) return;
    int p = (int)(idx % HW);
    long t = idx / HW;
    int c = (int)(t % FS);
    float div = expf((float)((c >> 1) * 2) * (-9.210340371976184f / 256.0f));
    float ang = (float)p * div;
    buf[idx] += (c & 1) ? cosf(ang) : sinf(ang);
}

// ---------------- launch ----------------
static inline int cdiv(int a, int b) { return (a + b - 1) / b; }

extern "C" void kernel_launch(void* const* d_in, const int* in_sizes, int n_in,
                              void* d_out, int out_size)
{
    const float* C3 = (const float*)d_in[0];
    const float* C4 = (const float*)d_in[1];
    const float* C5 = (const float*)d_in[2];
    const float* S3 = (const float*)d_in[3];
    const float* S4 = (const float*)d_in[4];
    const float* S5 = (const float*)d_in[5];
    const float* w31 = (const float*)d_in[6],  *b31 = (const float*)d_in[7];
    const float* w32 = (const float*)d_in[8],  *b32 = (const float*)d_in[9];
    const float* w41 = (const float*)d_in[10], *b41 = (const float*)d_in[11];
    const float* w42 = (const float*)d_in[12], *b42 = (const float*)d_in[13];
    const float* w51 = (const float*)d_in[14], *b51 = (const float*)d_in[15];
    const float* w52 = (const float*)d_in[16], *b52 = (const float*)d_in[17];
    const float* w6  = (const float*)d_in[18], *b6  = (const float*)d_in[19];
    const float* w7  = (const float*)d_in[20], *b7  = (const float*)d_in[21];
    const float* wq  = (const float*)d_in[22], *bq  = (const float*)d_in[23];
    const float* wk  = (const float*)d_in[24], *bk  = (const float*)d_in[25];
    float* out = (float*)d_out;

    float *P3x, *P4x, *P5x, *P6x, *s3, *s4, *s5, *s6, *s7, *Qb, *Kb, *Scr;
    cudaGetSymbolAddress((void**)&P3x, g_P3x);
    cudaGetSymbolAddress((void**)&P4x, g_P4x);
    cudaGetSymbolAddress((void**)&P5x, g_P5x);
    cudaGetSymbolAddress((void**)&P6x, g_P6x);
    cudaGetSymbolAddress((void**)&s3,  g_s3);
    cudaGetSymbolAddress((void**)&s4,  g_s4);
    cudaGetSymbolAddress((void**)&s5,  g_s5);
    cudaGetSymbolAddress((void**)&s6,  g_s6);
    cudaGetSymbolAddress((void**)&s7,  g_s7);
    cudaGetSymbolAddress((void**)&Qb,  g_Qb);
    cudaGetSymbolAddress((void**)&Kb,  g_Kb);
    cudaGetSymbolAddress((void**)&Scr, g_scores);

    const long off3 = 0;
    const long off4 = off3 + (long)NB * 512 * 1600;
    const long off5 = off4 + (long)NB * 512 * 400;
    const long off6 = off5 + (long)NB * 512 * 100;
    const long off7 = off6 + (long)NB * 512 * 25;

    dim3 thr(256);

    // ---- lateral 1x1 convs (query + support)
    conv_gemm<1><<<dim3(cdiv(100,64), 4, NB),  thr>>>(C5, w51, b51, P5x, 2048,10,10,10,10,1,0, 2048L*100, 256L*100);
    conv_gemm<1><<<dim3(cdiv(400,64), 4, NB),  thr>>>(C4, w41, b41, P4x, 1024,20,20,20,20,1,0, 1024L*400, 256L*400);
    conv_gemm<1><<<dim3(cdiv(1600,64),4, NB),  thr>>>(C3, w31, b31, P3x,  512,40,40,40,40,1,0,  512L*1600,256L*1600);
    conv_gemm<1><<<dim3(cdiv(100,64), 4, NSB), thr>>>(S5, w51, b51, s5,  2048,10,10,10,10,1,0, 2048L*100, 256L*100);
    conv_gemm<1><<<dim3(cdiv(400,64), 4, NSB), thr>>>(S4, w41, b41, s4,  1024,20,20,20,20,1,0, 1024L*400, 256L*400);
    conv_gemm<1><<<dim3(cdiv(1600,64),4, NSB), thr>>>(S3, w31, b31, s3,   512,40,40,40,40,1,0,  512L*1600,256L*1600);

    // ---- P6 / P7 heads (3x3 stride 2; P7 takes relu(P6))
    conv_gemm<3><<<dim3(1, 4, NB),  thr>>>(C5,  w6, b6, P6x,        2048,10,10,5,5,2,0, 2048L*100, 256L*25);
    conv_gemm<3><<<dim3(1, 4, NSB), thr>>>(S5,  w6, b6, s6,         2048,10,10,5,5,2,0, 2048L*100, 256L*25);
    conv_gemm<3><<<dim3(1, 4, NB),  thr>>>(P6x, w7, b7, out + off7,  256, 5, 5,3,3,2,1,  256L*25,  512L*9);
    conv_gemm<3><<<dim3(1, 4, NSB), thr>>>(s6,  w7, b7, s7,          256, 5, 5,3,3,2,1,  256L*25,  256L*9);
    copy_qx<<<cdiv(NB*FS*25, 256), thr>>>(out + off6, P6x, 25);

    // ---- query top-down FPN + 3x3 convs into output qx halves
    up2_add<<<cdiv(NB*FS*400, 256),  thr>>>(P4x, P5x, NB*FS, 20, 20);
    conv_gemm<3><<<dim3(cdiv(100,64), 4, NB), thr>>>(P5x, w52, b52, out + off5, 256,10,10,10,10,1,0, 256L*100, 512L*100);
    up2_add<<<cdiv(NB*FS*1600, 256), thr>>>(P3x, P4x, NB*FS, 40, 40);
    conv_gemm<3><<<dim3(cdiv(400,64), 4, NB), thr>>>(P4x, w42, b42, out + off4, 256,20,20,20,20,1,0, 256L*400, 512L*400);
    conv_gemm<3><<<dim3(cdiv(1600,64),4, NB), thr>>>(P3x, w32, b32, out + off3, 256,40,40,40,40,1,0, 256L*1600,512L*1600);

    // ---- add positional encoding to support features (serves both K input and V)
    add_pe<<<cdiv(NSB*FS*1600, 256), thr>>>(s3, NSB, 1600);
    add_pe<<<cdiv(NSB*FS*400,  256), thr>>>(s4, NSB, 400);
    add_pe<<<cdiv(NSB*FS*100,  256), thr>>>(s5, NSB, 100);
    add_pe<<<cdiv(NSB*FS*25,   256), thr>>>(s6, NSB, 25);
    add_pe<<<cdiv(NSB*FS*9,    256), thr>>>(s7, NSB, 9);

    // ---- attention per level
    struct Lv { long off; float* sb; int L; };
    const Lv lv[5] = { {off3, s3, 1600}, {off4, s4, 400}, {off5, s5, 100},
                       {off6, s6, 25},   {off7, s7, 9} };
    const float scale = 0.0625f;  // 1/sqrt(256)

    for (int t = 0; t < 5; t++) {
        const int L = lv[t].L;
        float* qx = out + lv[t].off;          // [NB, 512, HW] — channels 0..255 are qx
        // Q[b, o, l]  (reads qx half of the output buffer)
        conv_gemm<1><<<dim3(cdiv(L,64), 4, NB),  thr>>>(qx,       wq, bq, Qb, 256, L,1, L,1, 1,0, 512L*L, 256L*L);
        // K[b*5+s, o, l]
        conv_gemm<1><<<dim3(cdiv(L,64), 4, NSB), thr>>>(lv[t].sb, wk, bk, Kb, 256, L,1, L,1, 1,0, 256L*L, 256L*L);
        // scores, softmax, PV
        scores_gemm<<<dim3(cdiv(L,64), cdiv(L,64), 40), thr>>>(Qb, Kb, Scr, L, scale);
        softmax_rows<<<40 * L, thr>>>(Scr, L);
        pv_gemm<<<dim3(cdiv(L,64), 4, NB), thr>>>(Scr, lv[t].sb, out + lv[t].off + 256L * L, L, 512L * L);
    }
}

// round 3
// speedup vs baseline: 1.0045x; 1.0045x over previous
#include <cuda_runtime.h>
#include <math.h>

#define NB 8
#define NSHOT 5
#define NSB 40          // NB * NSHOT
#define FS 256
#define TILE 64
#define KT 16

// ---------------- scratch (static device globals; no allocation at runtime) ----------------
__device__ float g_P3x[NB*FS*1600];
__device__ float g_P4x[NB*FS*400];
__device__ float g_P5x[NB*FS*100];
__device__ float g_P6x[NB*FS*25];
__device__ float g_s3[NSB*FS*1600];
__device__ float g_s4[NSB*FS*400];
__device__ float g_s5[NSB*FS*100];
__device__ float g_s6[NSB*FS*25];
__device__ float g_s7[NSB*FS*9];
__device__ float g_Qb[NB*FS*1600];
__device__ float g_Kb[NSB*FS*1600];
__device__ float g_scores[(size_t)NSHOT*NB*1600*1600];   // 409.6 MB, level-3 worst case

// ---------------- generic conv-as-GEMM (1x1 or 3x3 implicit im2col) ----------------
// Y[n, o, p] = bias[o] + sum_k W[o,k] * X(n, k-th unrolled input, p)
// Y channel stride = Hout*Wout; batch strides passed explicitly so Y can point
// into the final concatenated output buffer (channel-512 layout).
template<int KSIZE>
__global__ void conv_gemm(const float* __restrict__ X, const float* __restrict__ W,
                          const float* __restrict__ bias, float* __restrict__ Y,
                          int Cin, int Hin, int Win, int Hout, int Wout,
                          int stride, int reluIn, long xBatch, long yBatch)
{
    const int HWout = Hout * Wout;
    const int HWin  = Hin * Win;
    const int Ktot  = Cin * KSIZE * KSIZE;
    const int n  = blockIdx.z;
    const int m0 = blockIdx.y * TILE;       // output-channel tile (M = 256, always full)
    const int p0 = blockIdx.x * TILE;       // pixel tile
    const float* Xn = X + (long)n * xBatch;

    __shared__ float As[KT][TILE + 1];
    __shared__ float Bs[KT][TILE + 1];

    const int tid = threadIdx.x;            // 256 threads
    const int tx = tid & 15, ty = tid >> 4;
    float acc[4][4] = {};

    for (int kk = 0; kk < Ktot; kk += KT) {
        // A tile: W[m0+m][kk+k]  (K always divisible by 16 here)
        #pragma unroll
        for (int i = 0; i < 4; i++) {
            int lin = tid + i * 256;
            int m = lin >> 4, k = lin & 15;
            As[k][m] = W[(long)(m0 + m) * Ktot + kk + k];
        }
        // B tile: gathered input
        #pragma unroll
        for (int i = 0; i < 4; i++) {
            int lin = tid + i * 256;
            int k = lin >> 6, nn = lin & 63;
            int p = p0 + nn;
            float v = 0.f;
            if (p < HWout) {
                int gk = kk + k;
                if (KSIZE == 1) {
                    v = Xn[(long)gk * HWin + p];
                } else {
                    int c = gk / 9, tap = gk - c * 9;
                    int dy = tap / 3, dx = tap - dy * 3;
                    int py = p / Wout, px = p - py * Wout;
                    int iy = py * stride + dy - 1;
                    int ix = px * stride + dx - 1;
                    if (iy >= 0 && iy < Hin && ix >= 0 && ix < Win) {
                        v = Xn[(long)c * HWin + iy * Win + ix];
                        if (reluIn) v = fmaxf(v, 0.f);
                    }
                }
            }
            Bs[k][nn] = v;
        }
        __syncthreads();
        #pragma unroll
        for (int k = 0; k < KT; k++) {
            float a[4], b[4];
            #pragma unroll
            for (int i = 0; i < 4; i++) a[i] = As[k][ty * 4 + i];
            #pragma unroll
            for (int j = 0; j < 4; j++) b[j] = Bs[k][tx * 4 + j];
            #pragma unroll
            for (int i = 0; i < 4; i++)
                #pragma unroll
                for (int j = 0; j < 4; j++) acc[i][j] += a[i] * b[j];
        }
        __syncthreads();
    }

    float* Yn = Y + (long)n * yBatch;
    #pragma unroll
    for (int i = 0; i < 4; i++) {
        int o = m0 + ty * 4 + i;
        float bv = bias[o];
        #pragma unroll
        for (int j = 0; j < 4; j++) {
            int p = p0 + tx * 4 + j;
            if (p < HWout) Yn[(long)o * HWout + p] = acc[i][j] + bv;
        }
    }
}

// ---------------- scores: Scr[(s*8+b), l, m] = scale * sum_o Q[b,o,l]*K[b*5+s,o,m] ----------------
__global__ void scores_gemm(const float* __restrict__ Qg, const float* __restrict__ Kg,
                            float* __restrict__ Scr, int L, float scale)
{
    const int z = blockIdx.z;               // s*8 + b
    const int s = z >> 3, b = z & 7;
    const int l0 = blockIdx.y * TILE;
    const int m0 = blockIdx.x * TILE;
    const float* A  = Qg + (long)b * FS * L;
    const float* Bp = Kg + (long)(b * NSHOT + s) * FS * L;

    __shared__ float As[KT][TILE + 1];
    __shared__ float Bs[KT][TILE + 1];
    const int tid = threadIdx.x;
    const int tx = tid & 15, ty = tid >> 4;
    float acc[4][4] = {};

    for (int kk = 0; kk < FS; kk += KT) {
        #pragma unroll
        for (int i = 0; i < 4; i++) {
            int lin = tid + i * 256;
            int k = lin >> 6, c = lin & 63;
            As[k][c] = (l0 + c < L) ? A [(long)(kk + k) * L + l0 + c] : 0.f;
        }
        #pragma unroll
        for (int i = 0; i < 4; i++) {
            int lin = tid + i * 256;
            int k = lin >> 6, c = lin & 63;
            Bs[k][c] = (m0 + c < L) ? Bp[(long)(kk + k) * L + m0 + c] : 0.f;
        }
        __syncthreads();
        #pragma unroll
        for (int k = 0; k < KT; k++) {
            float a[4], b2[4];
            #pragma unroll
            for (int i = 0; i < 4; i++) a[i]  = As[k][ty * 4 + i];
            #pragma unroll
            for (int j = 0; j < 4; j++) b2[j] = Bs[k][tx * 4 + j];
            #pragma unroll
            for (int i = 0; i < 4; i++)
                #pragma unroll
                for (int j = 0; j < 4; j++) acc[i][j] += a[i] * b2[j];
        }
        __syncthreads();
    }
    #pragma unroll
    for (int i = 0; i < 4; i++) {
        int l = l0 + ty * 4 + i;
        #pragma unroll
        for (int j = 0; j < 4; j++) {
            int m = m0 + tx * 4 + j;
            if (l < L && m < L)
                Scr[((long)z * L + l) * L + m] = acc[i][j] * scale;
        }
    }
}

// ---------------- row softmax over last dim ----------------
__global__ void softmax_rows(float* __restrict__ S, int L)
{
    const long row = blockIdx.x;
    float* p = S + row * (long)L;
    __shared__ float red[256];
    const int tid = threadIdx.x;

    float mx = -1e30f;
    for (int i = tid; i < L; i += 256) mx = fmaxf(mx, p[i]);
    red[tid] = mx; __syncthreads();
    for (int st = 128; st > 0; st >>= 1) {
        if (tid < st) red[tid] = fmaxf(red[tid], red[tid + st]);
        __syncthreads();
    }
    mx = red[0]; __syncthreads();

    float sum = 0.f;
    for (int i = tid; i < L; i += 256) { float e = expf(p[i] - mx); p[i] = e; sum += e; }
    red[tid] = sum; __syncthreads();
    for (int st = 128; st > 0; st >>= 1) {
        if (tid < st) red[tid] += red[tid + st];
        __syncthreads();
    }
    const float inv = 1.f / red[0];
    for (int i = tid; i < L; i += 256) p[i] *= inv;
}

// ---------------- PV: out[b, 256+c, l] = (1/5) * sum_{s,m} Scr[s,b,l,m] * V[b*5+s, c, m] ----------------
__global__ void pv_gemm(const float* __restrict__ Scr, const float* __restrict__ V,
                        float* __restrict__ Ybase, int L, long yBatch)
{
    const int b  = blockIdx.z;
    const int c0 = blockIdx.y * TILE;
    const int l0 = blockIdx.x * TILE;
    const int Ktot = NSHOT * L;

    __shared__ float As[KT][TILE + 1];
    __shared__ float Bs[KT][TILE + 1];
    const int tid = threadIdx.x;
    const int tx = tid & 15, ty = tid >> 4;
    float acc[4][4] = {};

    for (int kk = 0; kk < Ktot; kk += KT) {
        #pragma unroll
        for (int i = 0; i < 4; i++) {
            int lin = tid + i * 256;
            int cl = lin >> 4, k = lin & 15;
            int gk = kk + k;
            float v = 0.f;
            if (gk < Ktot) {
                int s = gk / L, m = gk - s * L;
                v = V[((long)(b * NSHOT + s) * FS + (c0 + cl)) * L + m];
            }
            As[k][cl] = v;
        }
        #pragma unroll
        for (int i = 0; i < 4; i++) {
            int lin = tid + i * 256;
            int ll = lin >> 4, k = lin & 15;
            int gk = kk + k;
            int l = l0 + ll;
            float v = 0.f;
            if (gk < Ktot && l < L) {
                int s = gk / L, m = gk - s * L;
                v = Scr[(((long)(s * 8 + b)) * L + l) * L + m];
            }
            Bs[k][ll] = v;
        }
        __syncthreads();
        #pragma unroll
        for (int k = 0; k < KT; k++) {
            float a[4], b2[4];
            #pragma unroll
            for (int i = 0; i < 4; i++) a[i]  = As[k][ty * 4 + i];
            #pragma unroll
            for (int j = 0; j < 4; j++) b2[j] = Bs[k][tx * 4 + j];
            #pragma unroll
            for (int i = 0; i < 4; i++)
                #pragma unroll
                for (int j = 0; j < 4; j++) acc[i][j] += a[i] * b2[j];
        }
        __syncthreads();
    }

    float* Yn = Ybase + (long)b * yBatch;
    #pragma unroll
    for (int i = 0; i < 4; i++) {
        int c = c0 + ty * 4 + i;
        #pragma unroll
        for (int j = 0; j < 4; j++) {
            int l = l0 + tx * 4 + j;
            if (l < L) Yn[(long)c * L + l] = acc[i][j] * 0.2f;
        }
    }
}

// ---------------- elementwise helpers ----------------
__global__ void up2_add(float* __restrict__ dst, const float* __restrict__ src,
                        int NC, int Hd, int Wd)
{
    int idx = blockIdx.x * blockDim.x + threadIdx.x;
    int tot = NC * Hd * Wd;
    if (idx >= tot) return;
    int x = idx % Wd; int t = idx / Wd;
    int y = t % Hd;   int nc = t / Hd;
    dst[idx] += src[(nc * (Hd >> 1) + (y >> 1)) * (Wd >> 1) + (x >> 1)];
}

__global__ void copy_qx(float* __restrict__ out, const float* __restrict__ src, int HW)
{
    int idx = blockIdx.x * blockDim.x + threadIdx.x;
    int tot = NB * FS * HW;
    if (idx >= tot) return;
    int p = idx % HW; int t = idx / HW;
    int c = t % FS;   int b = t / FS;
    out[(long)b * 512 * HW + (long)c * HW + p] = src[idx];
}

__global__ void add_pe(float* __restrict__ buf, int N, int HW)
{
    long idx = blockIdx.x * (long)blockDim.x + threadIdx.x;
    long tot = (long)N * FS * HW;
    if (idx >= tot) return;
    int p = (int)(idx % HW);
    long t = idx / HW;
    int c = (int)(t % FS);
    float div = expf((float)((c >> 1) * 2) * (-9.210340371976184f / 256.0f));
    float ang = (float)p * div;
    buf[idx] += (c & 1) ? cosf(ang) : sinf(ang);
}

// ---------------- launch ----------------
static inline int cdiv(int a, int b) { return (a + b - 1) / b; }

extern "C" void kernel_launch(void* const* d_in, const int* in_sizes, int n_in,
                              void* d_out, int out_size)
{
    const float* C3 = (const float*)d_in[0];
    const float* C4 = (const float*)d_in[1];
    const float* C5 = (const float*)d_in[2];
    const float* S3 = (const float*)d_in[3];
    const float* S4 = (const float*)d_in[4];
    const float* S5 = (const float*)d_in[5];
    const float* w31 = (const float*)d_in[6],  *b31 = (const float*)d_in[7];
    const float* w32 = (const float*)d_in[8],  *b32 = (const float*)d_in[9];
    const float* w41 = (const float*)d_in[10], *b41 = (const float*)d_in[11];
    const float* w42 = (const float*)d_in[12], *b42 = (const float*)d_in[13];
    const float* w51 = (const float*)d_in[14], *b51 = (const float*)d_in[15];
    const float* w52 = (const float*)d_in[16], *b52 = (const float*)d_in[17];
    const float* w6  = (const float*)d_in[18], *b6  = (const float*)d_in[19];
    const float* w7  = (const float*)d_in[20], *b7  = (const float*)d_in[21];
    const float* wq  = (const float*)d_in[22], *bq  = (const float*)d_in[23];
    const float* wk  = (const float*)d_in[24], *bk  = (const float*)d_in[25];
    float* out = (float*)d_out;

    float *P3x, *P4x, *P5x, *P6x, *s3, *s4, *s5, *s6, *s7, *Qb, *Kb, *Scr;
    cudaGetSymbolAddress((void**)&P3x, g_P3x);
    cudaGetSymbolAddress((void**)&P4x, g_P4x);
    cudaGetSymbolAddress((void**)&P5x, g_P5x);
    cudaGetSymbolAddress((void**)&P6x, g_P6x);
    cudaGetSymbolAddress((void**)&s3,  g_s3);
    cudaGetSymbolAddress((void**)&s4,  g_s4);
    cudaGetSymbolAddress((void**)&s5,  g_s5);
    cudaGetSymbolAddress((void**)&s6,  g_s6);
    cudaGetSymbolAddress((void**)&s7,  g_s7);
    cudaGetSymbolAddress((void**)&Qb,  g_Qb);
    cudaGetSymbolAddress((void**)&Kb,  g_Kb);
    cudaGetSymbolAddress((void**)&Scr, g_scores);

    const long off3 = 0;
    const long off4 = off3 + (long)NB * 512 * 1600;
    const long off5 = off4 + (long)NB * 512 * 400;
    const long off6 = off5 + (long)NB * 512 * 100;
    const long off7 = off6 + (long)NB * 512 * 25;

    dim3 thr(256);

    // ---- lateral 1x1 convs (query + support)
    conv_gemm<1><<<dim3(cdiv(100,64), 4, NB),  thr>>>(C5, w51, b51, P5x, 2048,10,10,10,10,1,0, 2048L*100, 256L*100);
    conv_gemm<1><<<dim3(cdiv(400,64), 4, NB),  thr>>>(C4, w41, b41, P4x, 1024,20,20,20,20,1,0, 1024L*400, 256L*400);
    conv_gemm<1><<<dim3(cdiv(1600,64),4, NB),  thr>>>(C3, w31, b31, P3x,  512,40,40,40,40,1,0,  512L*1600,256L*1600);
    conv_gemm<1><<<dim3(cdiv(100,64), 4, NSB), thr>>>(S5, w51, b51, s5,  2048,10,10,10,10,1,0, 2048L*100, 256L*100);
    conv_gemm<1><<<dim3(cdiv(400,64), 4, NSB), thr>>>(S4, w41, b41, s4,  1024,20,20,20,20,1,0, 1024L*400, 256L*400);
    conv_gemm<1><<<dim3(cdiv(1600,64),4, NSB), thr>>>(S3, w31, b31, s3,   512,40,40,40,40,1,0,  512L*1600,256L*1600);

    // ---- P6 / P7 heads (3x3 stride 2; P7 takes relu(P6))
    conv_gemm<3><<<dim3(1, 4, NB),  thr>>>(C5,  w6, b6, P6x,        2048,10,10,5,5,2,0, 2048L*100, 256L*25);
    conv_gemm<3><<<dim3(1, 4, NSB), thr>>>(S5,  w6, b6, s6,         2048,10,10,5,5,2,0, 2048L*100, 256L*25);
    conv_gemm<3><<<dim3(1, 4, NB),  thr>>>(P6x, w7, b7, out + off7,  256, 5, 5,3,3,2,1,  256L*25,  512L*9);
    conv_gemm<3><<<dim3(1, 4, NSB), thr>>>(s6,  w7, b7, s7,          256, 5, 5,3,3,2,1,  256L*25,  256L*9);
    copy_qx<<<cdiv(NB*FS*25, 256), thr>>>(out + off6, P6x, 25);

    // ---- query top-down FPN + 3x3 convs into output qx halves
    up2_add<<<cdiv(NB*FS*400, 256),  thr>>>(P4x, P5x, NB*FS, 20, 20);
    conv_gemm<3><<<dim3(cdiv(100,64), 4, NB), thr>>>(P5x, w52, b52, out + off5, 256,10,10,10,10,1,0, 256L*100, 512L*100);
    up2_add<<<cdiv(NB*FS*1600, 256), thr>>>(P3x, P4x, NB*FS, 40, 40);
    conv_gemm<3><<<dim3(cdiv(400,64), 4, NB), thr>>>(P4x, w42, b42, out + off4, 256,20,20,20,20,1,0, 256L*400, 512L*400);
    conv_gemm<3><<<dim3(cdiv(1600,64),4, NB), thr>>>(P3x, w32, b32, out + off3, 256,40,40,40,40,1,0, 256L*1600,512L*1600);

    // ---- add positional encoding to support features (serves both K input and V)
    add_pe<<<cdiv(NSB*FS*1600, 256), thr>>>(s3, NSB, 1600);
    add_pe<<<cdiv(NSB*FS*400,  256), thr>>>(s4, NSB, 400);
    add_pe<<<cdiv(NSB*FS*100,  256), thr>>>(s5, NSB, 100);
    add_pe<<<cdiv(NSB*FS*25,   256), thr>>>(s6, NSB, 25);
    add_pe<<<cdiv(NSB*FS*9,    256), thr>>>(s7, NSB, 9);

    // ---- attention per level
    struct Lv { long off; float* sb; int L; };
    const Lv lv[5] = { {off3, s3, 1600}, {off4, s4, 400}, {off5, s5, 100},
                       {off6, s6, 25},   {off7, s7, 9} };
    const float scale = 0.0625f;  // 1/sqrt(256)

    for (int t = 0; t < 5; t++) {
        const int L = lv[t].L;
        float* qx = out + lv[t].off;          // [NB, 512, HW] — channels 0..255 are qx
        // Q[b, o, l]  (reads qx half of the output buffer)
        conv_gemm<1><<<dim3(cdiv(L,64), 4, NB),  thr>>>(qx,       wq, bq, Qb, 256, L,1, L,1, 1,0, 512L*L, 256L*L);
        // K[b*5+s, o, l]
        conv_gemm<1><<<dim3(cdiv(L,64), 4, NSB), thr>>>(lv[t].sb, wk, bk, Kb, 256, L,1, L,1, 1,0, 256L*L, 256L*L);
        // scores, softmax, PV
        scores_gemm<<<dim3(cdiv(L,64), cdiv(L,64), 40), thr>>>(Qb, Kb, Scr, L, scale);
        softmax_rows<<<40 * L, thr>>>(Scr, L);
        pv_gemm<<<dim3(cdiv(L,64), 4, NB), thr>>>(Scr, lv[t].sb, out + lv[t].off + 256L * L, L, 512L * L);
    }
}